// round 3
// baseline (speedup 1.0000x reference)
#include <cuda_runtime.h>

#define NN 50000
#define NE 800000
#define H 128
#define ED 32
#define BN_EPS 1e-5f
#define RES_SCALE 0.1f

#define FMA2(d, a, b, c) \
    asm("fma.rn.f32x2 %0, %1, %2, %3;" : "=l"(d) : "l"(a), "l"(b), "l"(c))
#define PACK2(d, x, y) \
    asm("mov.b64 %0, {%1, %2};" : "=l"(d) : "r"(__float_as_uint(x)), "r"(__float_as_uint(y)))
#define PACKDUP(d, x) \
    asm("mov.b64 %0, {%1, %1};" : "=l"(d) : "r"(__float_as_uint(x)))
#define UNPACK2(x, y, d)                                  \
    do {                                                  \
        unsigned int _lo, _hi;                            \
        asm("mov.b64 {%0, %1}, %2;" : "=r"(_lo), "=r"(_hi) : "l"(d)); \
        x = __uint_as_float(_lo);                         \
        y = __uint_as_float(_hi);                         \
    } while (0)

typedef unsigned long long ull;

// ---------------- scratch (device globals; allocation-free) ----------------
__device__ __align__(16) float g_h[NN * H];
__device__ __align__(16) float g_z[NN * H];
__device__ __align__(16) float g_t[NN * H];
__device__ __align__(16) float g_z2[NN * H];
__device__ __align__(16) float g_eas[(size_t)NE * ED];  // ea gathered to CSR order
__device__ int g_src[NE];
__device__ int g_dstv[NE];
__device__ int g_eid[NE];
__device__ int g_ssort[NE];
__device__ int g_cnt[NN];
__device__ int g_rowptr[NN + 1];
__device__ int g_cursor[NN];
__device__ int g_bsum[64];
__device__ int g_boff[64];
__device__ __align__(16) float g_colsum[H];
__device__ __align__(16) float g_colsq[H];
__device__ __align__(16) float g_scale[H];
__device__ __align__(16) float g_shift[H];
__device__ int g_i64;

// ---------------- init: h = x, zero counts ----------------
__global__ void k_init(const float* __restrict__ x) {
    int i = blockIdx.x * blockDim.x + threadIdx.x;
    if (i < NN * H) g_h[i] = x[i];
    if (i < NN) g_cnt[i] = 0;
}

// int64 vs int32 edge_index detection (warp-parallel, 64 samples)
__global__ void k_detect(const int* __restrict__ p) {
    int lane = threadIdx.x;
    int v = p[2 * lane + 1] | p[2 * (lane + 32) + 1];
    unsigned bal = __ballot_sync(0xffffffffu, v != 0);
    if (lane == 0) g_i64 = (bal == 0);
}

// ---------------- CSR build ----------------
__global__ void k_prep(const int* __restrict__ p) {
    int e = blockIdx.x * blockDim.x + threadIdx.x;
    if (e >= NE) return;
    int s, d;
    if (g_i64) {
        const long long* q = (const long long*)p;
        s = (int)q[e];
        d = (int)q[NE + e];
    } else {
        s = p[e];
        d = p[NE + e];
    }
    g_src[e] = s;
    g_dstv[e] = d;
    atomicAdd(&g_cnt[d], 1);
}

// hierarchical scan: A) per-block sums  B) scan of block sums  C) block scans
__global__ void k_scanA() {
    __shared__ int ws[32];
    int tid = threadIdx.x, lane = tid & 31, wid = tid >> 5;
    int i = blockIdx.x * 1024 + tid;
    int v = (i < NN) ? g_cnt[i] : 0;
    int s = v;
#pragma unroll
    for (int o = 16; o > 0; o >>= 1) s += __shfl_down_sync(0xffffffffu, s, o);
    if (lane == 0) ws[wid] = s;
    __syncthreads();
    if (wid == 0) {
        int t = ws[lane];
#pragma unroll
        for (int o = 16; o > 0; o >>= 1) t += __shfl_down_sync(0xffffffffu, t, o);
        if (lane == 0) g_bsum[blockIdx.x] = t;
    }
}

__global__ void k_scanB(int nblk) {
    // single warp: sequential-ish scan of <=64 block sums
    int lane = threadIdx.x;
    int v0 = (lane < nblk) ? g_bsum[lane] : 0;
    int v1 = (lane + 32 < nblk) ? g_bsum[lane + 32] : 0;
    int s0 = v0;
#pragma unroll
    for (int o = 1; o < 32; o <<= 1) {
        int t = __shfl_up_sync(0xffffffffu, s0, o);
        if (lane >= o) s0 += t;
    }
    int tot0 = __shfl_sync(0xffffffffu, s0, 31);
    int s1 = v1;
#pragma unroll
    for (int o = 1; o < 32; o <<= 1) {
        int t = __shfl_up_sync(0xffffffffu, s1, o);
        if (lane >= o) s1 += t;
    }
    s1 += tot0;
    if (lane < nblk) g_boff[lane] = s0 - v0;
    if (lane + 32 < nblk) g_boff[lane + 32] = s1 - v1;
    int total = (nblk <= 32) ? __shfl_sync(0xffffffffu, s0, nblk - 1)
                             : __shfl_sync(0xffffffffu, s1, nblk - 33);
    if (lane == 0) g_rowptr[NN] = total;
}

__global__ void k_scanC() {
    __shared__ int ws[32];
    int tid = threadIdx.x, lane = tid & 31, wid = tid >> 5;
    int i = blockIdx.x * 1024 + tid;
    int v = (i < NN) ? g_cnt[i] : 0;
    int s = v;
#pragma unroll
    for (int o = 1; o < 32; o <<= 1) {
        int t = __shfl_up_sync(0xffffffffu, s, o);
        if (lane >= o) s += t;
    }
    if (lane == 31) ws[wid] = s;
    __syncthreads();
    if (wid == 0) {
        int t = ws[lane];
#pragma unroll
        for (int o = 1; o < 32; o <<= 1) {
            int u = __shfl_up_sync(0xffffffffu, t, o);
            if (lane >= o) t += u;
        }
        ws[lane] = t;
    }
    __syncthreads();
    int excl = s - v + (wid > 0 ? ws[wid - 1] : 0) + g_boff[blockIdx.x];
    if (i < NN) {
        g_rowptr[i] = excl;
        g_cursor[i] = excl;
    }
}

__global__ void k_scatter() {
    int e = blockIdx.x * blockDim.x + threadIdx.x;
    if (e >= NE) return;
    int d = g_dstv[e];
    int pos = atomicAdd(&g_cursor[d], 1);
    g_eid[pos] = e;
    g_ssort[pos] = g_src[e];
}

// gather edge_attr rows into CSR order: warp j -> sorted slot j
__global__ void k_gather(const float* __restrict__ ea) {
    int idx = blockIdx.x * 256 + threadIdx.x;
    int j = idx >> 5;
    int lane = idx & 31;
    if (j >= NE) return;
    int e = g_eid[j];
    g_eas[(size_t)j * ED + lane] = ea[(size_t)e * ED + lane];
}

// ---------------- edge message + segment sum ----------------
// z = h + sum_{e->node} relu(h[src] + ea@We + be)
// 1 warp per node; lane owns 4 cols; We slice in registers; f32x2 FMA.
__global__ void __launch_bounds__(256) k_agg(const float* __restrict__ We,
                                             const float* __restrict__ be) {
    int tid = threadIdx.x;
    int lane = tid & 31;
    int w = tid >> 5;
    int node = blockIdx.x * 8 + w;
    int c0 = lane * 4;

    ull wk0[ED], wk1[ED];
#pragma unroll
    for (int k = 0; k < ED; k++) {
        const ull* wp = (const ull*)(We + (size_t)k * H + c0);
        wk0[k] = wp[0];
        wk1[k] = wp[1];
    }
    if (node >= NN) return;

    float4 bv = *(const float4*)(be + c0);
    ull bias0, bias1;
    PACK2(bias0, bv.x, bv.y);
    PACK2(bias1, bv.z, bv.w);
    float4 acc = *(const float4*)(g_h + (size_t)node * H + c0);

    int beg = g_rowptr[node];
    int end = g_rowptr[node + 1];
    int s = 0, s2 = 0;
    float eav = 0.f;
    float4 hv = make_float4(0.f, 0.f, 0.f, 0.f);
    if (beg < end) {
        s = g_ssort[beg];
        eav = g_eas[(size_t)beg * ED + lane];
        hv = *(const float4*)(g_h + (size_t)s * H + c0);
        if (beg + 1 < end) s2 = g_ssort[beg + 1];
    }
    for (int j = beg; j < end; j++) {
        float ecur = eav;
        float4 hcur = hv;
        if (j + 1 < end) {
            eav = g_eas[(size_t)(j + 1) * ED + lane];
            hv = *(const float4*)(g_h + (size_t)s2 * H + c0);
            if (j + 2 < end) s2 = g_ssort[j + 2];
        }
        ull m0 = bias0, m1 = bias1;
#pragma unroll
        for (int k = 0; k < ED; k++) {
            float a = __shfl_sync(0xffffffffu, ecur, k);
            ull ap;
            PACKDUP(ap, a);
            FMA2(m0, ap, wk0[k], m0);
            FMA2(m1, ap, wk1[k], m1);
        }
        float mx, my, mz, mw;
        UNPACK2(mx, my, m0);
        UNPACK2(mz, mw, m1);
        acc.x += fmaxf(mx + hcur.x, 0.f);
        acc.y += fmaxf(my + hcur.y, 0.f);
        acc.z += fmaxf(mz + hcur.z, 0.f);
        acc.w += fmaxf(mw + hcur.w, 0.f);
    }
    *(float4*)(g_z + (size_t)node * H + c0) = acc;
}

// ---------------- 128x128-tile GEMM with f32x2: C = A @ W + b ----------------
// which==0: A=g_z -> C=g_t, relu, block0 zeroes BN stats
// which==1: A=g_t -> C=g_z2, no relu, fused BN sum/sumsq reduction
__global__ void __launch_bounds__(256) k_mlp(int which, const float* __restrict__ W,
                                             const float* __restrict__ bias) {
    const float* A = which ? g_t : g_z;
    float* C = which ? g_z2 : g_t;
    __shared__ float As[128 * 36];
    __shared__ float Ws[32 * 128];
    int tid = threadIdx.x;
    int tx = tid & 15;
    int ty = tid >> 4;
    int row0 = blockIdx.x * 128;

    if (which == 0 && blockIdx.x == 0 && tid < H) {
        g_colsum[tid] = 0.f;
        g_colsq[tid] = 0.f;
    }

    ull acc2[8][4];
#pragma unroll
    for (int j = 0; j < 8; j++)
#pragma unroll
        for (int c = 0; c < 4; c++) acc2[j][c] = 0ull;

    for (int kt = 0; kt < 4; kt++) {
        for (int i = tid; i < 1024; i += 256) {
            int r = i >> 3, c4 = i & 7;
            int gr = row0 + r;
            float4 v = make_float4(0.f, 0.f, 0.f, 0.f);
            if (gr < NN) v = *(const float4*)(A + (size_t)gr * H + kt * 32 + c4 * 4);
            *(float4*)(As + r * 36 + c4 * 4) = v;
        }
        for (int i = tid; i < 1024; i += 256) {
            int k = i >> 5, c4 = i & 31;
            *(float4*)(Ws + k * H + c4 * 4) =
                *(const float4*)(W + (size_t)(kt * 32 + k) * H + c4 * 4);
        }
        __syncthreads();
#pragma unroll
        for (int k = 0; k < 32; k++) {
            const ull* wp = (const ull*)(Ws + k * H + tx * 8);
            ull w0 = wp[0], w1 = wp[1], w2 = wp[2], w3 = wp[3];
#pragma unroll
            for (int j = 0; j < 8; j++) {
                float a = As[(ty * 8 + j) * 36 + k];
                ull ap;
                PACKDUP(ap, a);
                FMA2(acc2[j][0], ap, w0, acc2[j][0]);
                FMA2(acc2[j][1], ap, w1, acc2[j][1]);
                FMA2(acc2[j][2], ap, w2, acc2[j][2]);
                FMA2(acc2[j][3], ap, w3, acc2[j][3]);
            }
        }
        __syncthreads();
    }

    float4 b0 = *(const float4*)(bias + tx * 8);
    float4 b1 = *(const float4*)(bias + tx * 8 + 4);
    float bb[8] = {b0.x, b0.y, b0.z, b0.w, b1.x, b1.y, b1.z, b1.w};

    if (which == 0) {
#pragma unroll
        for (int j = 0; j < 8; j++) {
            int gr = row0 + ty * 8 + j;
            if (gr < NN) {
                float o[8];
#pragma unroll
                for (int c = 0; c < 4; c++) UNPACK2(o[2 * c], o[2 * c + 1], acc2[j][c]);
#pragma unroll
                for (int c = 0; c < 8; c++) o[c] = fmaxf(o[c] + bb[c], 0.f);
                *(float4*)(C + (size_t)gr * H + tx * 8) = *(float4*)&o[0];
                *(float4*)(C + (size_t)gr * H + tx * 8 + 4) = *(float4*)&o[4];
            }
        }
    } else {
        float psum[8], psq[8];
#pragma unroll
        for (int c = 0; c < 8; c++) { psum[c] = 0.f; psq[c] = 0.f; }
#pragma unroll
        for (int j = 0; j < 8; j++) {
            int gr = row0 + ty * 8 + j;
            if (gr < NN) {
                float o[8];
#pragma unroll
                for (int c = 0; c < 4; c++) UNPACK2(o[2 * c], o[2 * c + 1], acc2[j][c]);
#pragma unroll
                for (int c = 0; c < 8; c++) o[c] += bb[c];
                *(float4*)(C + (size_t)gr * H + tx * 8) = *(float4*)&o[0];
                *(float4*)(C + (size_t)gr * H + tx * 8 + 4) = *(float4*)&o[4];
#pragma unroll
                for (int c = 0; c < 8; c++) {
                    psum[c] += o[c];
                    psq[c] = fmaf(o[c], o[c], psq[c]);
                }
            }
        }
        __syncthreads();
        float* Ssum = As;  // 16 x 128
        float* Ssq = Ws;   // 16 x 128
#pragma unroll
        for (int c = 0; c < 8; c++) {
            Ssum[ty * H + tx * 8 + c] = psum[c];
            Ssq[ty * H + tx * 8 + c] = psq[c];
        }
        __syncthreads();
        if (tid < H) {
            float s = 0.f, q = 0.f;
#pragma unroll
            for (int r = 0; r < 16; r++) {
                s += Ssum[r * H + tid];
                q += Ssq[r * H + tid];
            }
            atomicAdd(&g_colsum[tid], s);
            atomicAdd(&g_colsq[tid], q);
        }
    }
}

// ---------------- BN finalize ----------------
__global__ void k_bnfin(const float* __restrict__ gamma,
                        const float* __restrict__ beta) {
    int c = threadIdx.x;
    float mu = g_colsum[c] * (1.f / NN);
    float var = g_colsq[c] * (1.f / NN) - mu * mu;
    float rs = rsqrtf(var + BN_EPS);
    float sc = rs * gamma[c];
    g_scale[c] = sc;
    g_shift[c] = beta[c] - mu * sc;
}

// ---------------- BN apply + relu + residual ----------------
__global__ void k_post(float* __restrict__ dout, int use_dout) {
    int i = blockIdx.x * blockDim.x + threadIdx.x;
    if (i >= NN * H / 4) return;
    int c4 = i & 31;
    float4 z = ((const float4*)g_z2)[i];
    float4 sc = ((const float4*)g_scale)[c4];
    float4 sh = ((const float4*)g_shift)[c4];
    float4 hr = ((const float4*)g_h)[i];
    float4 o;
    o.x = fmaxf(fmaf(z.x, sc.x, sh.x), 0.f) + RES_SCALE * hr.x;
    o.y = fmaxf(fmaf(z.y, sc.y, sh.y), 0.f) + RES_SCALE * hr.y;
    o.z = fmaxf(fmaf(z.z, sc.z, sh.z), 0.f) + RES_SCALE * hr.z;
    o.w = fmaxf(fmaf(z.w, sc.w, sh.w), 0.f) + RES_SCALE * hr.w;
    float4* out = use_dout ? (float4*)dout : (float4*)g_h;
    out[i] = o;
}

// ---------------- launch ----------------
extern "C" void kernel_launch(void* const* d_in, const int* in_sizes, int n_in,
                              void* d_out, int out_size) {
    const float* x = (const float*)d_in[0];
    const int* ei = (const int*)d_in[1];
    const float* ea = (const float*)d_in[2];
    const float* We = (const float*)d_in[3];
    const float* be = (const float*)d_in[4];
    const float* W1 = (const float*)d_in[5];
    const float* b1 = (const float*)d_in[6];
    const float* W2 = (const float*)d_in[7];
    const float* b2 = (const float*)d_in[8];
    const float* gamma = (const float*)d_in[9];
    const float* beta = (const float*)d_in[10];

    const int SCAN_BLOCKS = (NN + 1023) / 1024;  // 49

    k_init<<<(NN * H + 255) / 256, 256>>>(x);
    k_detect<<<1, 32>>>(ei);
    k_prep<<<(NE + 255) / 256, 256>>>(ei);
    k_scanA<<<SCAN_BLOCKS, 1024>>>();
    k_scanB<<<1, 32>>>(SCAN_BLOCKS);
    k_scanC<<<SCAN_BLOCKS, 1024>>>();
    k_scatter<<<(NE + 255) / 256, 256>>>();
    k_gather<<<(NE * 32 + 255) / 256, 256>>>(ea);

    for (int l = 0; l < 3; l++) {
        k_agg<<<(NN + 7) / 8, 256>>>(We + (size_t)l * ED * H, be + (size_t)l * H);
        k_mlp<<<(NN + 127) / 128, 256>>>(0, W1 + (size_t)l * H * H, b1 + (size_t)l * H);
        k_mlp<<<(NN + 127) / 128, 256>>>(1, W2 + (size_t)l * H * H, b2 + (size_t)l * H);
        k_bnfin<<<1, 128>>>(gamma + (size_t)l * H, beta + (size_t)l * H);
        k_post<<<(NN * H / 4 + 255) / 256, 256>>>((float*)d_out, l == 2 ? 1 : 0);
    }
}

// round 4
// speedup vs baseline: 1.2621x; 1.2621x over previous
#include <cuda_runtime.h>

#define NN 50000
#define NE 800000
#define H 128
#define ED 32
#define BN_EPS 1e-5f
#define RES_SCALE 0.1f

// ---------------- scratch (device globals; allocation-free) ----------------
__device__ __align__(16) float g_h[NN * H];
__device__ __align__(16) float g_z[NN * H];
__device__ __align__(16) float g_t[NN * H];
__device__ __align__(16) float g_z2[NN * H];
__device__ __align__(16) float g_eas[(size_t)NE * ED];  // ea gathered to CSR order
__device__ int g_src[NE];
__device__ int g_dstv[NE];
__device__ int g_eid[NE];
__device__ int g_ssort[NE];
__device__ int g_cnt[NN];
__device__ int g_rowptr[NN + 1];
__device__ int g_cursor[NN];
__device__ int g_bsum[64];
__device__ int g_boff[64];
__device__ __align__(16) float g_colsum[H];
__device__ __align__(16) float g_colsq[H];
__device__ __align__(16) float g_scale[H];
__device__ __align__(16) float g_shift[H];
__device__ int g_i64;

// ---------------- init: h = x, zero counts ----------------
__global__ void k_init(const float* __restrict__ x) {
    int i = blockIdx.x * blockDim.x + threadIdx.x;
    if (i < NN * H) g_h[i] = x[i];
    if (i < NN) g_cnt[i] = 0;
}

// int64 vs int32 edge_index detection (warp-parallel, 64 samples)
__global__ void k_detect(const int* __restrict__ p) {
    int lane = threadIdx.x;
    int v = p[2 * lane + 1] | p[2 * (lane + 32) + 1];
    unsigned bal = __ballot_sync(0xffffffffu, v != 0);
    if (lane == 0) g_i64 = (bal == 0);
}

// ---------------- CSR build ----------------
__global__ void k_prep(const int* __restrict__ p) {
    int e = blockIdx.x * blockDim.x + threadIdx.x;
    if (e >= NE) return;
    int s, d;
    if (g_i64) {
        const long long* q = (const long long*)p;
        s = (int)q[e];
        d = (int)q[NE + e];
    } else {
        s = p[e];
        d = p[NE + e];
    }
    g_src[e] = s;
    g_dstv[e] = d;
    atomicAdd(&g_cnt[d], 1);
}

// hierarchical scan: A) per-block sums  B) scan of block sums  C) block scans
__global__ void k_scanA() {
    __shared__ int ws[32];
    int tid = threadIdx.x, lane = tid & 31, wid = tid >> 5;
    int i = blockIdx.x * 1024 + tid;
    int v = (i < NN) ? g_cnt[i] : 0;
    int s = v;
#pragma unroll
    for (int o = 16; o > 0; o >>= 1) s += __shfl_down_sync(0xffffffffu, s, o);
    if (lane == 0) ws[wid] = s;
    __syncthreads();
    if (wid == 0) {
        int t = ws[lane];
#pragma unroll
        for (int o = 16; o > 0; o >>= 1) t += __shfl_down_sync(0xffffffffu, t, o);
        if (lane == 0) g_bsum[blockIdx.x] = t;
    }
}

__global__ void k_scanB(int nblk) {
    int lane = threadIdx.x;
    int v0 = (lane < nblk) ? g_bsum[lane] : 0;
    int v1 = (lane + 32 < nblk) ? g_bsum[lane + 32] : 0;
    int s0 = v0;
#pragma unroll
    for (int o = 1; o < 32; o <<= 1) {
        int t = __shfl_up_sync(0xffffffffu, s0, o);
        if (lane >= o) s0 += t;
    }
    int tot0 = __shfl_sync(0xffffffffu, s0, 31);
    int s1 = v1;
#pragma unroll
    for (int o = 1; o < 32; o <<= 1) {
        int t = __shfl_up_sync(0xffffffffu, s1, o);
        if (lane >= o) s1 += t;
    }
    s1 += tot0;
    if (lane < nblk) g_boff[lane] = s0 - v0;
    if (lane + 32 < nblk) g_boff[lane + 32] = s1 - v1;
    int total = (nblk <= 32) ? __shfl_sync(0xffffffffu, s0, nblk - 1)
                             : __shfl_sync(0xffffffffu, s1, nblk - 33);
    if (lane == 0) g_rowptr[NN] = total;
}

__global__ void k_scanC() {
    __shared__ int ws[32];
    int tid = threadIdx.x, lane = tid & 31, wid = tid >> 5;
    int i = blockIdx.x * 1024 + tid;
    int v = (i < NN) ? g_cnt[i] : 0;
    int s = v;
#pragma unroll
    for (int o = 1; o < 32; o <<= 1) {
        int t = __shfl_up_sync(0xffffffffu, s, o);
        if (lane >= o) s += t;
    }
    if (lane == 31) ws[wid] = s;
    __syncthreads();
    if (wid == 0) {
        int t = ws[lane];
#pragma unroll
        for (int o = 1; o < 32; o <<= 1) {
            int u = __shfl_up_sync(0xffffffffu, t, o);
            if (lane >= o) t += u;
        }
        ws[lane] = t;
    }
    __syncthreads();
    int excl = s - v + (wid > 0 ? ws[wid - 1] : 0) + g_boff[blockIdx.x];
    if (i < NN) {
        g_rowptr[i] = excl;
        g_cursor[i] = excl;
    }
}

__global__ void k_scatter() {
    int e = blockIdx.x * blockDim.x + threadIdx.x;
    if (e >= NE) return;
    int d = g_dstv[e];
    int pos = atomicAdd(&g_cursor[d], 1);
    g_eid[pos] = e;
    g_ssort[pos] = g_src[e];
}

// gather edge_attr rows into CSR order: warp j -> sorted slot j
__global__ void k_gather(const float* __restrict__ ea) {
    int idx = blockIdx.x * 256 + threadIdx.x;
    int j = idx >> 5;
    int lane = idx & 31;
    if (j >= NE) return;
    int e = g_eid[j];
    g_eas[(size_t)j * ED + lane] = ea[(size_t)e * ED + lane];
}

// ---------------- edge message + segment sum ----------------
// z = h + sum_{e->node} relu(h[src] + ea@We + be)
// 2 warps per node; each warp owns 64 cols; weights in registers (proven R2
// shape), but edge features now streamed from CSR-ordered g_eas (coalesced,
// no g_eid indirection in the hot loop).
__global__ void __launch_bounds__(256) k_agg(const float* __restrict__ We,
                                             const float* __restrict__ be) {
    int tid = threadIdx.x;
    int lane = tid & 31;
    int w = tid >> 5;                  // 0..7
    int node = blockIdx.x * 4 + (w >> 1);
    int half = w & 1;
    int c0 = half * 64 + lane * 2;

    float2 wreg[ED];
#pragma unroll
    for (int k = 0; k < ED; k++)
        wreg[k] = *(const float2*)(We + (size_t)k * H + c0);

    if (node >= NN) return;
    float2 bias = *(const float2*)(be + c0);
    float2 acc = *(const float2*)(g_h + (size_t)node * H + c0);

    int beg = g_rowptr[node];
    int end = g_rowptr[node + 1];
    int s = 0, s2 = 0;
    float eav = 0.f;
    float2 hv = make_float2(0.f, 0.f);
    if (beg < end) {
        s = g_ssort[beg];
        eav = g_eas[(size_t)beg * ED + lane];
        hv = *(const float2*)(g_h + (size_t)s * H + c0);
        if (beg + 1 < end) s2 = g_ssort[beg + 1];
    }
    for (int j = beg; j < end; j++) {
        float ecur = eav;
        float2 hcur = hv;
        if (j + 1 < end) {
            eav = g_eas[(size_t)(j + 1) * ED + lane];
            hv = *(const float2*)(g_h + (size_t)s2 * H + c0);
            if (j + 2 < end) s2 = g_ssort[j + 2];
        }
        float mx = bias.x, my = bias.y;
#pragma unroll
        for (int k = 0; k < ED; k++) {
            float a = __shfl_sync(0xffffffffu, ecur, k);
            mx = fmaf(a, wreg[k].x, mx);
            my = fmaf(a, wreg[k].y, my);
        }
        acc.x += fmaxf(mx + hcur.x, 0.f);
        acc.y += fmaxf(my + hcur.y, 0.f);
    }
    *(float2*)(g_z + (size_t)node * H + c0) = acc;
}

// ---------------- 128x128-tile GEMM: C = A @ W + b (proven R2 shape) -------
// which==0: A=g_z -> C=g_t, relu, block0 zeroes BN stats
// which==1: A=g_t -> C=g_z2, no relu, fused BN sum/sumsq reduction
__global__ void __launch_bounds__(256) k_mlp(int which, const float* __restrict__ W,
                                             const float* __restrict__ bias) {
    const float* A = which ? g_t : g_z;
    float* C = which ? g_z2 : g_t;
    __shared__ float As[128 * 36];
    __shared__ float Ws[32 * 128];
    int tid = threadIdx.x;
    int tx = tid & 15;
    int ty = tid >> 4;
    int row0 = blockIdx.x * 128;

    if (which == 0 && blockIdx.x == 0 && tid < H) {
        g_colsum[tid] = 0.f;
        g_colsq[tid] = 0.f;
    }

    float acc[8][8];
#pragma unroll
    for (int j = 0; j < 8; j++)
#pragma unroll
        for (int c = 0; c < 8; c++) acc[j][c] = 0.f;

    for (int kt = 0; kt < 4; kt++) {
        for (int i = tid; i < 1024; i += 256) {
            int r = i >> 3, c4 = i & 7;
            int gr = row0 + r;
            float4 v = make_float4(0.f, 0.f, 0.f, 0.f);
            if (gr < NN) v = *(const float4*)(A + (size_t)gr * H + kt * 32 + c4 * 4);
            *(float4*)(As + r * 36 + c4 * 4) = v;
        }
        for (int i = tid; i < 1024; i += 256) {
            int k = i >> 5, c4 = i & 31;
            *(float4*)(Ws + k * H + c4 * 4) =
                *(const float4*)(W + (size_t)(kt * 32 + k) * H + c4 * 4);
        }
        __syncthreads();
#pragma unroll
        for (int k = 0; k < 32; k++) {
            float4 w0 = *(const float4*)(Ws + k * H + tx * 8);
            float4 w1 = *(const float4*)(Ws + k * H + tx * 8 + 4);
            float a[8];
#pragma unroll
            for (int j = 0; j < 8; j++) a[j] = As[(ty * 8 + j) * 36 + k];
#pragma unroll
            for (int j = 0; j < 8; j++) {
                acc[j][0] = fmaf(a[j], w0.x, acc[j][0]);
                acc[j][1] = fmaf(a[j], w0.y, acc[j][1]);
                acc[j][2] = fmaf(a[j], w0.z, acc[j][2]);
                acc[j][3] = fmaf(a[j], w0.w, acc[j][3]);
                acc[j][4] = fmaf(a[j], w1.x, acc[j][4]);
                acc[j][5] = fmaf(a[j], w1.y, acc[j][5]);
                acc[j][6] = fmaf(a[j], w1.z, acc[j][6]);
                acc[j][7] = fmaf(a[j], w1.w, acc[j][7]);
            }
        }
        __syncthreads();
    }

    float4 b0 = *(const float4*)(bias + tx * 8);
    float4 b1 = *(const float4*)(bias + tx * 8 + 4);

    if (which == 0) {
#pragma unroll
        for (int j = 0; j < 8; j++) {
            int gr = row0 + ty * 8 + j;
            if (gr < NN) {
                float4 o0, o1;
                o0.x = fmaxf(acc[j][0] + b0.x, 0.f);
                o0.y = fmaxf(acc[j][1] + b0.y, 0.f);
                o0.z = fmaxf(acc[j][2] + b0.z, 0.f);
                o0.w = fmaxf(acc[j][3] + b0.w, 0.f);
                o1.x = fmaxf(acc[j][4] + b1.x, 0.f);
                o1.y = fmaxf(acc[j][5] + b1.y, 0.f);
                o1.z = fmaxf(acc[j][6] + b1.z, 0.f);
                o1.w = fmaxf(acc[j][7] + b1.w, 0.f);
                *(float4*)(C + (size_t)gr * H + tx * 8) = o0;
                *(float4*)(C + (size_t)gr * H + tx * 8 + 4) = o1;
            }
        }
    } else {
        float psum[8], psq[8];
#pragma unroll
        for (int c = 0; c < 8; c++) { psum[c] = 0.f; psq[c] = 0.f; }
#pragma unroll
        for (int j = 0; j < 8; j++) {
            int gr = row0 + ty * 8 + j;
            if (gr < NN) {
                float o[8];
                o[0] = acc[j][0] + b0.x; o[1] = acc[j][1] + b0.y;
                o[2] = acc[j][2] + b0.z; o[3] = acc[j][3] + b0.w;
                o[4] = acc[j][4] + b1.x; o[5] = acc[j][5] + b1.y;
                o[6] = acc[j][6] + b1.z; o[7] = acc[j][7] + b1.w;
                *(float4*)(C + (size_t)gr * H + tx * 8) = *(float4*)&o[0];
                *(float4*)(C + (size_t)gr * H + tx * 8 + 4) = *(float4*)&o[4];
#pragma unroll
                for (int c = 0; c < 8; c++) {
                    psum[c] += o[c];
                    psq[c] = fmaf(o[c], o[c], psq[c]);
                }
            }
        }
        __syncthreads();
        float* Ssum = As;  // 16 x 128
        float* Ssq = Ws;   // 16 x 128
#pragma unroll
        for (int c = 0; c < 8; c++) {
            Ssum[ty * H + tx * 8 + c] = psum[c];
            Ssq[ty * H + tx * 8 + c] = psq[c];
        }
        __syncthreads();
        if (tid < H) {
            float s = 0.f, q = 0.f;
#pragma unroll
            for (int r = 0; r < 16; r++) {
                s += Ssum[r * H + tid];
                q += Ssq[r * H + tid];
            }
            atomicAdd(&g_colsum[tid], s);
            atomicAdd(&g_colsq[tid], q);
        }
    }
}

// ---------------- BN finalize ----------------
__global__ void k_bnfin(const float* __restrict__ gamma,
                        const float* __restrict__ beta) {
    int c = threadIdx.x;
    float mu = g_colsum[c] * (1.f / NN);
    float var = g_colsq[c] * (1.f / NN) - mu * mu;
    float rs = rsqrtf(var + BN_EPS);
    float sc = rs * gamma[c];
    g_scale[c] = sc;
    g_shift[c] = beta[c] - mu * sc;
}

// ---------------- BN apply + relu + residual ----------------
__global__ void k_post(float* __restrict__ dout, int use_dout) {
    int i = blockIdx.x * blockDim.x + threadIdx.x;
    if (i >= NN * H / 4) return;
    int c4 = i & 31;
    float4 z = ((const float4*)g_z2)[i];
    float4 sc = ((const float4*)g_scale)[c4];
    float4 sh = ((const float4*)g_shift)[c4];
    float4 hr = ((const float4*)g_h)[i];
    float4 o;
    o.x = fmaxf(fmaf(z.x, sc.x, sh.x), 0.f) + RES_SCALE * hr.x;
    o.y = fmaxf(fmaf(z.y, sc.y, sh.y), 0.f) + RES_SCALE * hr.y;
    o.z = fmaxf(fmaf(z.z, sc.z, sh.z), 0.f) + RES_SCALE * hr.z;
    o.w = fmaxf(fmaf(z.w, sc.w, sh.w), 0.f) + RES_SCALE * hr.w;
    float4* out = use_dout ? (float4*)dout : (float4*)g_h;
    out[i] = o;
}

// ---------------- launch ----------------
extern "C" void kernel_launch(void* const* d_in, const int* in_sizes, int n_in,
                              void* d_out, int out_size) {
    const float* x = (const float*)d_in[0];
    const int* ei = (const int*)d_in[1];
    const float* ea = (const float*)d_in[2];
    const float* We = (const float*)d_in[3];
    const float* be = (const float*)d_in[4];
    const float* W1 = (const float*)d_in[5];
    const float* b1 = (const float*)d_in[6];
    const float* W2 = (const float*)d_in[7];
    const float* b2 = (const float*)d_in[8];
    const float* gamma = (const float*)d_in[9];
    const float* beta = (const float*)d_in[10];

    const int SCAN_BLOCKS = (NN + 1023) / 1024;  // 49

    k_init<<<(NN * H + 255) / 256, 256>>>(x);
    k_detect<<<1, 32>>>(ei);
    k_prep<<<(NE + 255) / 256, 256>>>(ei);
    k_scanA<<<SCAN_BLOCKS, 1024>>>();
    k_scanB<<<1, 32>>>(SCAN_BLOCKS);
    k_scanC<<<SCAN_BLOCKS, 1024>>>();
    k_scatter<<<(NE + 255) / 256, 256>>>();
    k_gather<<<(NE * 32 + 255) / 256, 256>>>(ea);

    for (int l = 0; l < 3; l++) {
        k_agg<<<(NN + 3) / 4, 256>>>(We + (size_t)l * ED * H, be + (size_t)l * H);
        k_mlp<<<(NN + 127) / 128, 256>>>(0, W1 + (size_t)l * H * H, b1 + (size_t)l * H);
        k_mlp<<<(NN + 127) / 128, 256>>>(1, W2 + (size_t)l * H * H, b2 + (size_t)l * H);
        k_bnfin<<<1, 128>>>(gamma + (size_t)l * H, beta + (size_t)l * H);
        k_post<<<(NN * H / 4 + 255) / 256, 256>>>((float*)d_out, l == 2 ? 1 : 0);
    }
}